// round 1
// baseline (speedup 1.0000x reference)
#include <cuda_runtime.h>
#include <cuda_bf16.h>

// ---------------- problem constants ----------------
#define T_LEN   (1 << 21)              // 2,097,152 timesteps
#define L_STEPS 256                    // steps per chain
#define B_CHAINS (T_LEN / L_STEPS)     // 8192 chains
#define GPT 2                          // chains per thread (ILP)
#define SCAN_THREADS (B_CHAINS / GPT)  // 4096
#define SCAN_BLOCK 128
#define SCAN_GRID (SCAN_THREADS / SCAN_BLOCK)  // 32 blocks

#define RED_BLOCKS 1024
#define RED_THREADS 256

// ---------------- device scratch (no allocation allowed) ----------------
__device__ float2 g_tpte[T_LEN];          // warp-transposed (tanh(p_n/x1), tanh(e_n/x1))
__device__ float  g_send[2][B_CHAINS];    // ping-pong block end states
__device__ float  g_part[RED_BLOCKS * 8]; // reduction partials
__device__ float  g_stats[8];             // mu[4], inv_sigma[4]

// transposed index: chains grouped 32 per warp, step-major inside group
__device__ __forceinline__ int tr_idx(int c, int i) {
    return ((c >> 5) << 13) | (i << 5) | (c & 31);   // 32*L_STEPS = 8192 = 1<<13
}

// ---------------- one GR4J production-store step ----------------
__device__ __forceinline__ void gr_step(float& s, float tp, float tn,
                                        float& p_s_out, float& perc_out) {
    const float inv_x1 = 1.0f / 350.0f;
    float r   = s * inv_x1;
    // p_s = x1*(1-r^2)*tp / (1 + r*tp)
    float ps  = __fdividef(350.0f * (1.0f - r * r) * tp, fmaf(r, tp, 1.0f));
    // e_s = s*(2-r)*tn / (1 + (1-r)*tn)
    float es  = __fdividef(s * (2.0f - r) * tn, fmaf(1.0f - r, tn, 1.0f));
    float s1  = s + ps - es;
    // perc = s1*(1 - (1+u)^{-1/4}),  u = (4/9 * s1/x1)^4
    // cancellation-free: 1-w = u / (b*(1+w)*(1+w^2)),  w = b^{-1/4}, b = 1+u
    float y   = s1 * (4.0f / (9.0f * 350.0f));
    float y2  = y * y;
    float u   = y2 * y2;
    float b   = 1.0f + u;
    float q   = rsqrtf(b);          // b^{-1/2}
    float w   = q * rsqrtf(q);      // sqrt(q) = b^{-1/4}
    float den = b * (1.0f + w) * fmaf(w, w, 1.0f);
    float pc  = __fdividef(s1 * u, den);
    p_s_out  = ps;
    perc_out = pc;
    s = s1 - pc;
}

// ---------------- pass 0: elementwise prologue ----------------
__global__ void k_precompute(const float2* __restrict__ x, float* __restrict__ out) {
    int t = blockIdx.x * blockDim.x + threadIdx.x;
    float2 v = x[t];
    float pn = fmaxf(v.x - v.y, 0.0f);
    float en = fmaxf(v.y - v.x, 0.0f);
    reinterpret_cast<float2*>(out)[2 * t] = make_float2(pn, en);  // out cols 0,1 (raw)
    float tp = tanhf(pn * (1.0f / 350.0f));
    float te = tanhf(en * (1.0f / 350.0f));
    int c = t >> 8;          // t / L_STEPS
    int i = t & (L_STEPS - 1);
    g_tpte[tr_idx(c, i)] = make_float2(tp, te);
}

// ---------------- refinement pass: recompute block end states ----------------
__global__ void __launch_bounds__(SCAN_BLOCK) k_refine(int srcIdx, int dstIdx, int first) {
    int tid = blockIdx.x * blockDim.x + threadIdx.x;
    float s[GPT];
    int   base[GPT];
    int   c[GPT];
#pragma unroll
    for (int g = 0; g < GPT; g++) {
        c[g] = tid + g * SCAN_THREADS;
        base[g] = ((c[g] >> 5) << 13) | (c[g] & 31);
        s[g] = (first || c[g] == 0) ? 0.0f : g_send[srcIdx][c[g] - 1];
    }
#pragma unroll 4
    for (int i = 0; i < L_STEPS; i++) {
#pragma unroll
        for (int g = 0; g < GPT; g++) {
            float2 tt = g_tpte[base[g] + (i << 5)];
            float ps, pc;
            gr_step(s[g], tt.x, tt.y, ps, pc);
        }
    }
#pragma unroll
    for (int g = 0; g < GPT; g++) g_send[dstIdx][c[g]] = s[g];
}

// ---------------- final pass: replay scan, write outputs ----------------
__global__ void __launch_bounds__(SCAN_BLOCK) k_final(int srcIdx,
                                                      float* __restrict__ out,
                                                      float* __restrict__ sstore) {
    int tid = blockIdx.x * blockDim.x + threadIdx.x;
    float s[GPT];
    int   base[GPT];
    int   c[GPT];
#pragma unroll
    for (int g = 0; g < GPT; g++) {
        c[g] = tid + g * SCAN_THREADS;
        base[g] = ((c[g] >> 5) << 13) | (c[g] & 31);
        s[g] = (c[g] == 0) ? 0.0f : g_send[srcIdx][c[g] - 1];
    }
#pragma unroll 2
    for (int i = 0; i < L_STEPS; i++) {
#pragma unroll
        for (int g = 0; g < GPT; g++) {
            float2 tt = g_tpte[base[g] + (i << 5)];
            float ps, pc;
            gr_step(s[g], tt.x, tt.y, ps, pc);
            int t = c[g] * L_STEPS + i;
            reinterpret_cast<float2*>(out)[2 * t + 1] = make_float2(ps, pc); // cols 2,3
            sstore[t] = s[g];
        }
    }
}

// ---------------- deterministic column sums (stage 1) ----------------
__global__ void __launch_bounds__(RED_THREADS) k_reduce(const float4* __restrict__ out4) {
    float acc[8];
#pragma unroll
    for (int k = 0; k < 8; k++) acc[k] = 0.0f;
    for (int t = blockIdx.x * blockDim.x + threadIdx.x; t < T_LEN;
         t += gridDim.x * blockDim.x) {
        float4 v = out4[t];
        acc[0] += v.x; acc[1] += v.x * v.x;
        acc[2] += v.y; acc[3] += v.y * v.y;
        acc[4] += v.z; acc[5] += v.z * v.z;
        acc[6] += v.w; acc[7] += v.w * v.w;
    }
    __shared__ float sd[8][RED_THREADS];
    int tx = threadIdx.x;
#pragma unroll
    for (int k = 0; k < 8; k++) sd[k][tx] = acc[k];
    __syncthreads();
    for (int off = RED_THREADS / 2; off > 0; off >>= 1) {
        if (tx < off) {
#pragma unroll
            for (int k = 0; k < 8; k++) sd[k][tx] += sd[k][tx + off];
        }
        __syncthreads();
    }
    if (tx == 0) {
#pragma unroll
        for (int k = 0; k < 8; k++) g_part[blockIdx.x * 8 + k] = sd[k][0];
    }
}

// ---------------- stage 2: mu / inv_sigma ----------------
__global__ void __launch_bounds__(RED_THREADS) k_stats() {
    float acc[8];
#pragma unroll
    for (int k = 0; k < 8; k++) acc[k] = 0.0f;
    int tx = threadIdx.x;
    for (int b = tx; b < RED_BLOCKS; b += RED_THREADS) {
#pragma unroll
        for (int k = 0; k < 8; k++) acc[k] += g_part[b * 8 + k];
    }
    __shared__ float sd[8][RED_THREADS];
#pragma unroll
    for (int k = 0; k < 8; k++) sd[k][tx] = acc[k];
    __syncthreads();
    for (int off = RED_THREADS / 2; off > 0; off >>= 1) {
        if (tx < off) {
#pragma unroll
            for (int k = 0; k < 8; k++) sd[k][tx] += sd[k][tx + off];
        }
        __syncthreads();
    }
    if (tx == 0) {
        const float invT = 1.0f / (float)T_LEN;
#pragma unroll
        for (int k = 0; k < 4; k++) {
            float mu  = sd[2 * k][0] * invT;
            float var = sd[2 * k + 1][0] * invT - mu * mu;
            var = fmaxf(var, 0.0f);
            g_stats[k]     = mu;
            g_stats[4 + k] = 1.0f / sqrtf(var);
        }
    }
}

// ---------------- normalize out columns in place ----------------
__global__ void k_normalize(float4* __restrict__ out4) {
    __shared__ float st[8];
    if (threadIdx.x < 8) st[threadIdx.x] = g_stats[threadIdx.x];
    __syncthreads();
    int t = blockIdx.x * blockDim.x + threadIdx.x;
    float4 v = out4[t];
    v.x = (v.x - st[0]) * st[4];
    v.y = (v.y - st[1]) * st[5];
    v.z = (v.z - st[2]) * st[6];
    v.w = (v.w - st[3]) * st[7];
    out4[t] = v;
}

// ---------------- launch ----------------
extern "C" void kernel_launch(void* const* d_in, const int* in_sizes, int n_in,
                              void* d_out, int out_size) {
    (void)in_sizes; (void)n_in; (void)out_size;
    const float2* x = (const float2*)d_in[0];
    float* out    = (float*)d_out;                 // (T,4) row-major
    float* sstore = out + 4 * (size_t)T_LEN;       // (T,1) appended

    k_precompute<<<T_LEN / 256, 256>>>(x, out);

    // 4 relaxation sweeps over block end states (contraction >= e^-2.6 per sweep)
    k_refine<<<SCAN_GRID, SCAN_BLOCK>>>(0, 0, 1);
    k_refine<<<SCAN_GRID, SCAN_BLOCK>>>(0, 1, 0);
    k_refine<<<SCAN_GRID, SCAN_BLOCK>>>(1, 0, 0);
    k_refine<<<SCAN_GRID, SCAN_BLOCK>>>(0, 1, 0);

    k_final<<<SCAN_GRID, SCAN_BLOCK>>>(1, out, sstore);

    k_reduce<<<RED_BLOCKS, RED_THREADS>>>((const float4*)out);
    k_stats<<<1, RED_THREADS>>>();
    k_normalize<<<T_LEN / 256, 256>>>((float4*)out);
}